// round 14
// baseline (speedup 1.0000x reference)
#include <cuda_runtime.h>
#include <cuda_fp16.h>
#include <cstdint>

#define TE 128
#define NTE 512
#define NNODE_MAX 50000

// Static device scratch (no runtime alloc)
__device__ __half g_W1abT[512 * 128];       // UV weights [n=512][k=128] (U|V)
__device__ __half g_W1T[256 * 256];         // edge L1 (diff|prod) [n=256][k=256]
__device__ __half g_W2T[128 * 256];         // [n=128][k=256]
__device__ __half g_UV[(size_t)NNODE_MAX * 512];  // per-node U|V, f16 (51.2 MB)

// ---------------- helpers ----------------
__device__ __forceinline__ uint32_t smem_u32(const void* p) {
    uint32_t a;
    asm("{ .reg .u64 t; cvta.to.shared.u64 t, %1; cvt.u32.u64 %0, t; }" : "=r"(a) : "l"(p));
    return a;
}
__device__ __forceinline__ uint32_t f2h2(float lo, float hi) {
    uint32_t r;
    asm("cvt.rn.f16x2.f32 %0, %1, %2;" : "=r"(r) : "f"(hi), "f"(lo));
    return r;
}
#define CP_ASYNC16(dst_u32, src_ptr) \
    asm volatile("cp.async.cg.shared.global [%0], [%1], 16;" :: "r"(dst_u32), "l"(src_ptr) : "memory")
#define CP_COMMIT() asm volatile("cp.async.commit_group;" ::: "memory")
#define CP_WAIT(n)  asm volatile("cp.async.wait_group %0;" :: "n"(n) : "memory")

__device__ __forceinline__ void mma16(float* c, const uint32_t* a, uint32_t b0, uint32_t b1) {
    asm volatile(
        "mma.sync.aligned.m16n8k16.row.col.f32.f16.f16.f32 "
        "{%0,%1,%2,%3}, {%4,%5,%6,%7}, {%8,%9}, {%0,%1,%2,%3};"
        : "+f"(c[0]), "+f"(c[1]), "+f"(c[2]), "+f"(c[3])
        : "r"(a[0]), "r"(a[1]), "r"(a[2]), "r"(a[3]), "r"(b0), "r"(b1));
}
__device__ __forceinline__ void ldm4(uint32_t* r, uint32_t addr) {
    asm volatile("ldmatrix.sync.aligned.m8n8.x4.shared.b16 {%0,%1,%2,%3}, [%4];"
                 : "=r"(r[0]), "=r"(r[1]), "=r"(r[2]), "=r"(r[3]) : "r"(addr));
}
__device__ __forceinline__ uint32_t habs_sub2(uint32_t a, uint32_t b) {
    __half2 r = __habs2(__hsub2(*(__half2*)&a, *(__half2*)&b));
    return *(uint32_t*)&r;
}
__device__ __forceinline__ uint32_t hmul2u(uint32_t a, uint32_t b) {
    __half2 r = __hmul2(*(__half2*)&a, *(__half2*)&b);
    return *(uint32_t*)&r;
}

// ---------------- smem layout (BYTE offsets), edge kernel ----------------
#define STRH   272       // [128 rows][128 f16 + 16B pad]
#define STRX   528       // x1 [128 rows][256 f16 + 16B pad]
#define WBLK   34816     // one weight block: [128 n][STRH]
#define OFF_HI 0
#define OFF_HJ 34816
#define OFF_W  69632     // 2 x WBLK
#define OFF_X1 139264    // 67,584
#define OFF_SRC 206848   // int[128]
#define OFF_DST 207360   // int[128]
#define OFF_B2  207872   // f32[128]
#define OFF_W3  208384   // f32[256]
#define OFF_B3  209408   // f32[2]
#define SMEM_BYTES 209416

// ---------------- prep 1: round + transpose weights ----------------
__global__ void prep_w(const float* __restrict__ W1, const float* __restrict__ W2) {
    int i = blockIdx.x * blockDim.x + threadIdx.x;
    if (i < 512 * 128) {                       // W1abT [n=512][k=128]
        int n = i >> 7, k = i & 127;
        float v = (n < 256) ? W1[k * 256 + n] : W1[(128 + k) * 256 + (n - 256)];
        g_W1abT[i] = __float2half_rn(v);
    } else if (i < 512 * 128 + 256 * 256) {    // W1T (diff|prod) [n=256][k=256]
        int j = i - 512 * 128;
        int n = j >> 8, k = j & 255;
        float v = (k < 128) ? W1[(256 + k) * 256 + n] : W1[(384 + (k - 128)) * 256 + n];
        g_W1T[j] = __float2half_rn(v);
    } else {
        int j = i - 512 * 128 - 256 * 256;     // W2T [n=128][k=256]
        if (j < 128 * 256) {
            int n = j >> 8, k = j & 255;
            g_W2T[j] = __float2half_rn(W2[k * 128 + n]);
        }
    }
}

// ---------------- prep 2: UV = node @ [W1a|W1b] (+b1 folded into U) ----------------
#define UV_SMEM 70656
__global__ __launch_bounds__(256, 1)
void uv_kernel(const float* __restrict__ node, const float* __restrict__ b1, int nnode) {
    extern __shared__ char smc[];
    const uint32_t smb = smem_u32(smc);
    float* s_b1 = (float*)(smc + 69632);
    const int tid = threadIdx.x, lane = tid & 31;
    const int g = lane >> 2, t = lane & 3;
    const int wid = tid >> 5, wm = wid >> 2, wn = wid & 3;
    const int nb = blockIdx.y;
    const int r0 = blockIdx.x * 128;

    #pragma unroll
    for (int i = 0; i < 16; i++) {
        int idx = tid + i * 256;
        int m = idx >> 5, c4 = idx & 31;
        int nr = min(r0 + m, nnode - 1);
        float4 v = ((const float4*)node)[(size_t)nr * 32 + c4];
        *(uint2*)(smc + m * STRH + c4 * 8) = make_uint2(f2h2(v.x, v.y), f2h2(v.z, v.w));
    }
    #pragma unroll
    for (int i = 0; i < 8; i++) {
        int idx = tid + i * 256;
        int n = idx >> 4, q = idx & 15;
        *(uint4*)(smc + 34816 + n * STRH + q * 16) =
            *(const uint4*)(g_W1abT + (size_t)(nb * 128 + n) * 128 + q * 8);
    }
    for (int i = tid; i < 256; i += 256) s_b1[i] = b1[i];
    __syncthreads();

    float acc[4][4][4];
    #pragma unroll
    for (int mt = 0; mt < 4; mt++)
        #pragma unroll
        for (int nt = 0; nt < 4; nt++) {
            int col = wn * 32 + nt * 8 + 2 * t;
            int gc = nb * 128 + col;
            float v0 = (nb < 2) ? s_b1[gc] : 0.f;
            float v1 = (nb < 2) ? s_b1[gc + 1] : 0.f;
            acc[mt][nt][0] = v0; acc[mt][nt][1] = v1;
            acc[mt][nt][2] = v0; acc[mt][nt][3] = v1;
        }

    const int aRow = lane & 15;
    const int aKoff = ((lane >> 4) << 3) * 2;
    const uint32_t aBase = smb + (wm * 64 + aRow) * STRH + aKoff;
    const int nl = ((lane >> 4) << 3) + (lane & 7);
    const uint32_t bOff = (lane & 8) ? 16u : 0u;

    #pragma unroll
    for (int s = 0; s < 8; s++) {
        uint32_t aF[4][4];
        #pragma unroll
        for (int mt = 0; mt < 4; mt++)
            ldm4(aF[mt], aBase + mt * (16 * STRH) + s * 32);
        uint32_t bF[2][4];
        #pragma unroll
        for (int np = 0; np < 2; np++)
            ldm4(bF[np], smb + 34816 + (wn * 32 + np * 16 + nl) * STRH + bOff + s * 32);
        #pragma unroll
        for (int mt = 0; mt < 4; mt++) {
            mma16(acc[mt][0], aF[mt], bF[0][0], bF[0][1]);
            mma16(acc[mt][1], aF[mt], bF[0][2], bF[0][3]);
            mma16(acc[mt][2], aF[mt], bF[1][0], bF[1][1]);
            mma16(acc[mt][3], aF[mt], bF[1][2], bF[1][3]);
        }
    }

    #pragma unroll
    for (int mt = 0; mt < 4; mt++) {
        int m = wm * 64 + mt * 16 + g;
        #pragma unroll
        for (int nt = 0; nt < 4; nt++) {
            int col = wn * 32 + nt * 8 + 2 * t;
            if (r0 + m < nnode)
                *(uint32_t*)((char*)g_UV + ((size_t)(r0 + m) * 512 + nb * 128 + col) * 2) =
                    f2h2(acc[mt][nt][0], acc[mt][nt][1]);
            if (r0 + m + 8 < nnode)
                *(uint32_t*)((char*)g_UV + ((size_t)(r0 + m + 8) * 512 + nb * 128 + col) * 2) =
                    f2h2(acc[mt][nt][2], acc[mt][nt][3]);
        }
    }
}

// ---------------- edge kernel weight block loads (6 x 32KB, 512 thr) ----------------
__device__ __forceinline__ void issue_blk(uint32_t smb, int tid, int i) {
    const int d = i & 1;
    const __half* base;
    if (i < 4) base = g_W1T + (size_t)((i >> 1) * 128) * 256 + (i & 1) * 128;
    else       base = g_W2T + (size_t)(i - 4) * 128;
    #pragma unroll
    for (int j = 0; j < 4; j++) {
        int idx = tid + j * NTE;          // 0..2047
        int n = idx >> 4, q = idx & 15;
        CP_ASYNC16(smb + OFF_W + d * WBLK + n * STRH + q * 16,
                   base + (size_t)n * 256 + q * 8);
    }
}

// ---------------- main fused edge MLP: 512 threads, 16 warps (4/SMSP) ----------------
__global__ __launch_bounds__(NTE, 1)
void edge_mlp_512(const float* __restrict__ node,
                  const int*   __restrict__ src,
                  const int*   __restrict__ dst,
                  const float* __restrict__ b2,
                  const float* __restrict__ W3,
                  const float* __restrict__ b3,
                  float* __restrict__ out, int E)
{
    extern __shared__ char smc[];
    const uint32_t smb = smem_u32(smc);
    float* smf = (float*)smc;
    int* s_src = (int*)(smc + OFF_SRC);
    int* s_dst = (int*)(smc + OFF_DST);

    const int tid = threadIdx.x, lane = tid & 31;
    const int g = lane >> 2, t = lane & 3;
    const int wid = tid >> 5;
    const int wm = wid >> 2, wn = wid & 3;      // 4(M:32 rows) x 4(N:32 cols)
    const int e0 = blockIdx.x * TE;
    const int nedge = min(TE, E - e0);

    issue_blk(smb, tid, 0); CP_COMMIT();
    issue_blk(smb, tid, 1); CP_COMMIT();

    // gather h_i/h_j -> f16 smem (one rounding); src/dst to smem
    #pragma unroll 4
    for (int i = 0; i < 8; i++) {
        int idx = tid + i * NTE;
        int m = idx >> 5, c4 = idx & 31;
        int e = min(e0 + m, E - 1);
        int si = src[e], di = dst[e];
        if (c4 == 0) { s_src[m] = si; s_dst[m] = di; }
        float4 vi = ((const float4*)node)[(size_t)si * 32 + c4];
        float4 vj = ((const float4*)node)[(size_t)di * 32 + c4];
        *(uint2*)(smc + OFF_HI + m * STRH + c4 * 8) =
            make_uint2(f2h2(vi.x, vi.y), f2h2(vi.z, vi.w));
        *(uint2*)(smc + OFF_HJ + m * STRH + c4 * 8) =
            make_uint2(f2h2(vj.x, vj.y), f2h2(vj.z, vj.w));
    }
    for (int i = tid; i < 128; i += NTE) smf[OFF_B2 / 4 + i] = b2[i];
    for (int i = tid; i < 256; i += NTE) smf[OFF_W3 / 4 + i] = W3[i];
    if (tid < 2) smf[OFF_B3 / 4 + tid] = b3[tid];
    __syncthreads();

    const int aRow = lane & 15;
    const int aKoff = ((lane >> 4) << 3) * 2;
    const uint32_t hiBase = smb + OFF_HI + (wm * 32 + aRow) * STRH + aKoff;
    const uint32_t hjBase = smb + OFF_HJ + (wm * 32 + aRow) * STRH + aKoff;
    const uint32_t xBase  = smb + OFF_X1 + (wm * 32 + aRow) * STRX + aKoff;
    const int nl = ((lane >> 4) << 3) + (lane & 7);
    const uint32_t bOff = (lane & 8) ? 16u : 0u;

    // ================= layer 1: two n-halves, 2 weight-block phases each =================
    for (int h = 0; h < 2; h++) {
        // acc init = UV[src].U + UV[dst].V   (b1 folded into U)
        float accL1[2][4][4];
        #pragma unroll
        for (int mt = 0; mt < 2; mt++) {
            int r0 = wm * 32 + mt * 16 + g;
            const __half* U0 = g_UV + (size_t)s_src[r0] * 512;
            const __half* V0 = g_UV + (size_t)s_dst[r0] * 512 + 256;
            const __half* U1 = g_UV + (size_t)s_src[r0 + 8] * 512;
            const __half* V1 = g_UV + (size_t)s_dst[r0 + 8] * 512 + 256;
            #pragma unroll
            for (int nt = 0; nt < 4; nt++) {
                int c = h * 128 + wn * 32 + nt * 8 + 2 * t;
                float2 u0 = __half22float2(*(const __half2*)(U0 + c));
                float2 v0 = __half22float2(*(const __half2*)(V0 + c));
                float2 u1 = __half22float2(*(const __half2*)(U1 + c));
                float2 v1 = __half22float2(*(const __half2*)(V1 + c));
                accL1[mt][nt][0] = u0.x + v0.x; accL1[mt][nt][1] = u0.y + v0.y;
                accL1[mt][nt][2] = u1.x + v1.x; accL1[mt][nt][3] = u1.y + v1.y;
            }
        }

        #pragma unroll
        for (int p = 0; p < 2; p++) {
            const int ph = h * 2 + p, d = ph & 1;
            CP_WAIT(1);
            __syncthreads();

            #pragma unroll
            for (int s = 0; s < 8; s++) {
                uint32_t fi[2][4], fj[2][4], aF[2][4];
                #pragma unroll
                for (int mt = 0; mt < 2; mt++) {
                    ldm4(fi[mt], hiBase + mt * (16 * STRH) + s * 32);
                    ldm4(fj[mt], hjBase + mt * (16 * STRH) + s * 32);
                }
                #pragma unroll
                for (int mt = 0; mt < 2; mt++)
                    #pragma unroll
                    for (int x = 0; x < 4; x++)
                        aF[mt][x] = p ? hmul2u(fi[mt][x], fj[mt][x])
                                      : habs_sub2(fi[mt][x], fj[mt][x]);
                uint32_t bF[2][4];
                #pragma unroll
                for (int np = 0; np < 2; np++)
                    ldm4(bF[np], smb + OFF_W + d * WBLK
                                 + (wn * 32 + np * 16 + nl) * STRH + bOff + s * 32);
                #pragma unroll
                for (int mt = 0; mt < 2; mt++) {
                    mma16(accL1[mt][0], aF[mt], bF[0][0], bF[0][1]);
                    mma16(accL1[mt][1], aF[mt], bF[0][2], bF[0][3]);
                    mma16(accL1[mt][2], aF[mt], bF[1][0], bF[1][1]);
                    mma16(accL1[mt][3], aF[mt], bF[1][2], bF[1][3]);
                }
            }
            __syncthreads();
            if (ph + 2 <= 5) { issue_blk(smb, tid, ph + 2); CP_COMMIT(); }
        }

        // x1 = f16(relu(acc)) -> smem
        #pragma unroll
        for (int mt = 0; mt < 2; mt++) {
            int r = wm * 32 + mt * 16 + g;
            #pragma unroll
            for (int nt = 0; nt < 4; nt++) {
                int col = h * 128 + wn * 32 + nt * 8 + 2 * t;
                float* A = accL1[mt][nt];
                *(uint32_t*)(smc + OFF_X1 + r * STRX + col * 2) =
                    f2h2(fmaxf(A[0], 0.f), fmaxf(A[1], 0.f));
                *(uint32_t*)(smc + OFF_X1 + (r + 8) * STRX + col * 2) =
                    f2h2(fmaxf(A[2], 0.f), fmaxf(A[3], 0.f));
            }
        }
    }

    // ================= layer 2: 2 weight-block phases =================
    float accL2[2][4][4];
    #pragma unroll
    for (int mt = 0; mt < 2; mt++)
        #pragma unroll
        for (int nt = 0; nt < 4; nt++) {
            int col = wn * 32 + nt * 8 + 2 * t;
            float v0 = smf[OFF_B2 / 4 + col], v1 = smf[OFF_B2 / 4 + col + 1];
            accL2[mt][nt][0] = v0; accL2[mt][nt][1] = v1;
            accL2[mt][nt][2] = v0; accL2[mt][nt][3] = v1;
        }

    #pragma unroll
    for (int p = 0; p < 2; p++) {
        const int ph = 4 + p, d = ph & 1;
        if (ph < 5) CP_WAIT(1); else CP_WAIT(0);
        __syncthreads();   // also orders x1 stores before reads

        #pragma unroll
        for (int s = 0; s < 8; s++) {
            uint32_t aF[2][4];
            #pragma unroll
            for (int mt = 0; mt < 2; mt++)
                ldm4(aF[mt], xBase + mt * (16 * STRX) + (p * 128 + s * 16) * 2);
            uint32_t bF[2][4];
            #pragma unroll
            for (int np = 0; np < 2; np++)
                ldm4(bF[np], smb + OFF_W + d * WBLK
                             + (wn * 32 + np * 16 + nl) * STRH + bOff + s * 32);
            #pragma unroll
            for (int mt = 0; mt < 2; mt++) {
                mma16(accL2[mt][0], aF[mt], bF[0][0], bF[0][1]);
                mma16(accL2[mt][1], aF[mt], bF[0][2], bF[0][3]);
                mma16(accL2[mt][2], aF[mt], bF[1][0], bF[1][1]);
                mma16(accL2[mt][3], aF[mt], bF[1][2], bF[1][3]);
            }
        }
        __syncthreads();
    }

    // ================= layer 3: register relu.W3 + quad shuffle-reduce =================
    float* s_red = (float*)(smc + OFF_W);   // weight region dead: [128][8] f32
    #pragma unroll
    for (int mt = 0; mt < 2; mt++) {
        int r = wm * 32 + mt * 16 + g;
        float p00 = 0.f, p01 = 0.f, p10 = 0.f, p11 = 0.f;
        #pragma unroll
        for (int nt = 0; nt < 4; nt++) {
            float* A = accL2[mt][nt];
            int col = wn * 32 + nt * 8 + 2 * t;
            float w00 = smf[OFF_W3 / 4 + 2 * col],     w01 = smf[OFF_W3 / 4 + 2 * col + 1];
            float w10 = smf[OFF_W3 / 4 + 2 * col + 2], w11 = smf[OFF_W3 / 4 + 2 * col + 3];
            float x0 = fmaxf(A[0], 0.f), x1v = fmaxf(A[1], 0.f);
            float x2v = fmaxf(A[2], 0.f), x3v = fmaxf(A[3], 0.f);
            p00 += x0 * w00 + x1v * w10;
            p01 += x0 * w01 + x1v * w11;
            p10 += x2v * w00 + x3v * w10;
            p11 += x2v * w01 + x3v * w11;
        }
        p00 += __shfl_xor_sync(0xFFFFFFFFu, p00, 1);
        p00 += __shfl_xor_sync(0xFFFFFFFFu, p00, 2);
        p01 += __shfl_xor_sync(0xFFFFFFFFu, p01, 1);
        p01 += __shfl_xor_sync(0xFFFFFFFFu, p01, 2);
        p10 += __shfl_xor_sync(0xFFFFFFFFu, p10, 1);
        p10 += __shfl_xor_sync(0xFFFFFFFFu, p10, 2);
        p11 += __shfl_xor_sync(0xFFFFFFFFu, p11, 1);
        p11 += __shfl_xor_sync(0xFFFFFFFFu, p11, 2);
        if (t == 0) {
            s_red[r * 8 + wn * 2 + 0] = p00;
            s_red[r * 8 + wn * 2 + 1] = p01;
            s_red[(r + 8) * 8 + wn * 2 + 0] = p10;
            s_red[(r + 8) * 8 + wn * 2 + 1] = p11;
        }
    }
    __syncthreads();

    if (tid < 2 * TE) {
        int row = tid >> 1, cc = tid & 1;
        float sum = smf[OFF_B3 / 4 + cc]
                  + s_red[row * 8 + 0 + cc] + s_red[row * 8 + 2 + cc]
                  + s_red[row * 8 + 4 + cc] + s_red[row * 8 + 6 + cc];
        if (row < nedge) out[(size_t)(e0 + row) * 2 + cc] = sum;
    }
}

extern "C" void kernel_launch(void* const* d_in, const int* in_sizes, int n_in,
                              void* d_out, int out_size)
{
    const float* node = (const float*)d_in[0];
    const int*   src  = (const int*)  d_in[1];
    const int*   dst  = (const int*)  d_in[2];
    const float* W1   = (const float*)d_in[3];
    const float* b1   = (const float*)d_in[4];
    const float* W2   = (const float*)d_in[5];
    const float* b2   = (const float*)d_in[6];
    const float* W3   = (const float*)d_in[7];
    const float* b3   = (const float*)d_in[8];
    float* out = (float*)d_out;

    const int E = in_sizes[1];
    const int nnode = in_sizes[0] / 128;

    {   // prep 1: weight rounding/transpose
        int total = 512 * 128 + 256 * 256 + 128 * 256;
        prep_w<<<(total + 255) / 256, 256>>>(W1, W2);
    }
    {   // prep 2: UV = node @ [W1a|W1b] + [b1|0]
        cudaFuncSetAttribute(uv_kernel,
                             cudaFuncAttributeMaxDynamicSharedMemorySize, UV_SMEM);
        dim3 grid((nnode + 127) / 128, 4);
        uv_kernel<<<grid, 256, UV_SMEM>>>(node, b1, nnode);
    }

    cudaFuncSetAttribute(edge_mlp_512,
                         cudaFuncAttributeMaxDynamicSharedMemorySize, SMEM_BYTES);
    const int grid = (E + TE - 1) / TE;
    edge_mlp_512<<<grid, NTE, SMEM_BYTES>>>(node, src, dst, b2, W3, b3, out, E);
}

// round 15
// speedup vs baseline: 1.4789x; 1.4789x over previous
#include <cuda_runtime.h>
#include <cuda_fp16.h>
#include <cstdint>

#define TE 128
#define NT 256
#define NNODE_MAX 50000

// Static device scratch (no runtime alloc)
__device__ __half g_W1abT[512 * 128];       // UV weights [n=512][k=128] (U|V)
__device__ __half g_W1T[256 * 256];         // edge L1 (diff|prod) [n=256][k=256]
__device__ __half g_W2T[128 * 256];         // [n=128][k=256]
__device__ __half g_UV[(size_t)NNODE_MAX * 512];  // per-node U|V, f16 (51.2 MB)

// ---------------- helpers ----------------
__device__ __forceinline__ uint32_t smem_u32(const void* p) {
    uint32_t a;
    asm("{ .reg .u64 t; cvta.to.shared.u64 t, %1; cvt.u32.u64 %0, t; }" : "=r"(a) : "l"(p));
    return a;
}
__device__ __forceinline__ uint32_t f2h2(float lo, float hi) {
    uint32_t r;
    asm("cvt.rn.f16x2.f32 %0, %1, %2;" : "=r"(r) : "f"(hi), "f"(lo));
    return r;
}
#define CP_ASYNC16(dst_u32, src_ptr) \
    asm volatile("cp.async.cg.shared.global [%0], [%1], 16;" :: "r"(dst_u32), "l"(src_ptr) : "memory")
#define CP_COMMIT() asm volatile("cp.async.commit_group;" ::: "memory")
#define CP_WAIT(n)  asm volatile("cp.async.wait_group %0;" :: "n"(n) : "memory")

__device__ __forceinline__ void mma16(float* c, const uint32_t* a, uint32_t b0, uint32_t b1) {
    asm volatile(
        "mma.sync.aligned.m16n8k16.row.col.f32.f16.f16.f32 "
        "{%0,%1,%2,%3}, {%4,%5,%6,%7}, {%8,%9}, {%0,%1,%2,%3};"
        : "+f"(c[0]), "+f"(c[1]), "+f"(c[2]), "+f"(c[3])
        : "r"(a[0]), "r"(a[1]), "r"(a[2]), "r"(a[3]), "r"(b0), "r"(b1));
}
__device__ __forceinline__ void ldm4(uint32_t* r, uint32_t addr) {
    asm volatile("ldmatrix.sync.aligned.m8n8.x4.shared.b16 {%0,%1,%2,%3}, [%4];"
                 : "=r"(r[0]), "=r"(r[1]), "=r"(r[2]), "=r"(r[3]) : "r"(addr));
}
__device__ __forceinline__ uint32_t habs_sub2(uint32_t a, uint32_t b) {
    __half2 r = __habs2(__hsub2(*(__half2*)&a, *(__half2*)&b));
    return *(uint32_t*)&r;
}
__device__ __forceinline__ uint32_t hmul2u(uint32_t a, uint32_t b) {
    __half2 r = __hmul2(*(__half2*)&a, *(__half2*)&b);
    return *(uint32_t*)&r;
}

// ---------------- smem layout (BYTE offsets), edge kernel ----------------
#define STRH   272       // [128 rows][128 f16 + 16B pad]
#define STRX   528       // x1 [128 rows][256 f16 + 16B pad]
#define WBLK   34816     // one weight block: [128 n][STRH]
#define OFF_HI 0
#define OFF_HJ 34816
#define OFF_W  69632     // 2 x WBLK
#define OFF_X1 139264    // 67,584
#define OFF_SRC 206848   // int[128]
#define OFF_DST 207360   // int[128]
#define OFF_B2  207872   // f32[128]
#define OFF_W3  208384   // f32[256]
#define OFF_B3  209408   // f32[2]
#define SMEM_BYTES 209416

// ---------------- prep 1: round + transpose weights ----------------
__global__ void prep_w(const float* __restrict__ W1, const float* __restrict__ W2) {
    int i = blockIdx.x * blockDim.x + threadIdx.x;
    if (i < 512 * 128) {                       // W1abT [n=512][k=128]
        int n = i >> 7, k = i & 127;
        float v = (n < 256) ? W1[k * 256 + n] : W1[(128 + k) * 256 + (n - 256)];
        g_W1abT[i] = __float2half_rn(v);
    } else if (i < 512 * 128 + 256 * 256) {    // W1T (diff|prod) [n=256][k=256]
        int j = i - 512 * 128;
        int n = j >> 8, k = j & 255;
        float v = (k < 128) ? W1[(256 + k) * 256 + n] : W1[(384 + (k - 128)) * 256 + n];
        g_W1T[j] = __float2half_rn(v);
    } else {
        int j = i - 512 * 128 - 256 * 256;     // W2T [n=128][k=256]
        if (j < 128 * 256) {
            int n = j >> 8, k = j & 255;
            g_W2T[j] = __float2half_rn(W2[k * 128 + n]);
        }
    }
}

// ---------------- prep 2: UV = node @ [W1a|W1b] (+b1 folded into U) ----------------
#define UV_SMEM 70656
__global__ __launch_bounds__(256, 1)
void uv_kernel(const float* __restrict__ node, const float* __restrict__ b1, int nnode) {
    extern __shared__ char smc[];
    const uint32_t smb = smem_u32(smc);
    float* s_b1 = (float*)(smc + 69632);
    const int tid = threadIdx.x, lane = tid & 31;
    const int g = lane >> 2, t = lane & 3;
    const int wid = tid >> 5, wm = wid >> 2, wn = wid & 3;
    const int nb = blockIdx.y;
    const int r0 = blockIdx.x * 128;

    #pragma unroll
    for (int i = 0; i < 16; i++) {
        int idx = tid + i * 256;
        int m = idx >> 5, c4 = idx & 31;
        int nr = min(r0 + m, nnode - 1);
        float4 v = ((const float4*)node)[(size_t)nr * 32 + c4];
        *(uint2*)(smc + m * STRH + c4 * 8) = make_uint2(f2h2(v.x, v.y), f2h2(v.z, v.w));
    }
    #pragma unroll
    for (int i = 0; i < 8; i++) {
        int idx = tid + i * 256;
        int n = idx >> 4, q = idx & 15;
        *(uint4*)(smc + 34816 + n * STRH + q * 16) =
            *(const uint4*)(g_W1abT + (size_t)(nb * 128 + n) * 128 + q * 8);
    }
    for (int i = tid; i < 256; i += 256) s_b1[i] = b1[i];
    __syncthreads();

    float acc[4][4][4];
    #pragma unroll
    for (int mt = 0; mt < 4; mt++)
        #pragma unroll
        for (int nt = 0; nt < 4; nt++) {
            int col = wn * 32 + nt * 8 + 2 * t;
            int gc = nb * 128 + col;
            float v0 = (nb < 2) ? s_b1[gc] : 0.f;
            float v1 = (nb < 2) ? s_b1[gc + 1] : 0.f;
            acc[mt][nt][0] = v0; acc[mt][nt][1] = v1;
            acc[mt][nt][2] = v0; acc[mt][nt][3] = v1;
        }

    const int aRow = lane & 15;
    const int aKoff = ((lane >> 4) << 3) * 2;
    const uint32_t aBase = smb + (wm * 64 + aRow) * STRH + aKoff;
    const int nl = ((lane >> 4) << 3) + (lane & 7);
    const uint32_t bOff = (lane & 8) ? 16u : 0u;

    #pragma unroll
    for (int s = 0; s < 8; s++) {
        uint32_t aF[4][4];
        #pragma unroll
        for (int mt = 0; mt < 4; mt++)
            ldm4(aF[mt], aBase + mt * (16 * STRH) + s * 32);
        uint32_t bF[2][4];
        #pragma unroll
        for (int np = 0; np < 2; np++)
            ldm4(bF[np], smb + 34816 + (wn * 32 + np * 16 + nl) * STRH + bOff + s * 32);
        #pragma unroll
        for (int mt = 0; mt < 4; mt++) {
            mma16(acc[mt][0], aF[mt], bF[0][0], bF[0][1]);
            mma16(acc[mt][1], aF[mt], bF[0][2], bF[0][3]);
            mma16(acc[mt][2], aF[mt], bF[1][0], bF[1][1]);
            mma16(acc[mt][3], aF[mt], bF[1][2], bF[1][3]);
        }
    }

    #pragma unroll
    for (int mt = 0; mt < 4; mt++) {
        int m = wm * 64 + mt * 16 + g;
        #pragma unroll
        for (int nt = 0; nt < 4; nt++) {
            int col = wn * 32 + nt * 8 + 2 * t;
            if (r0 + m < nnode)
                *(uint32_t*)((char*)g_UV + ((size_t)(r0 + m) * 512 + nb * 128 + col) * 2) =
                    f2h2(acc[mt][nt][0], acc[mt][nt][1]);
            if (r0 + m + 8 < nnode)
                *(uint32_t*)((char*)g_UV + ((size_t)(r0 + m + 8) * 512 + nb * 128 + col) * 2) =
                    f2h2(acc[mt][nt][2], acc[mt][nt][3]);
        }
    }
}

// ---------------- edge kernel weight block loads (6 x 32KB) ----------------
__device__ __forceinline__ void issue_blk(uint32_t smb, int tid, int i) {
    const int d = i & 1;
    const __half* base;
    if (i < 4) base = g_W1T + (size_t)((i >> 1) * 128) * 256 + (i & 1) * 128;
    else       base = g_W2T + (size_t)(i - 4) * 128;
    #pragma unroll
    for (int j = 0; j < 8; j++) {
        int idx = tid + j * NT;           // 0..2047
        int n = idx >> 4, q = idx & 15;
        CP_ASYNC16(smb + OFF_W + d * WBLK + n * STRH + q * 16,
                   base + (size_t)n * 256 + q * 8);
    }
}

// UV register prefetch: 64 scattered LDG.32, issued OFF the critical path.
__device__ __forceinline__ void prefetch_uv(uint32_t uvp[4][4][4], int h,
                                            const int* s_src, const int* s_dst,
                                            int wm, int wn, int g, int t) {
    const int co0 = wn * 16 + t;          // half2 index base within the 128-col half
    #pragma unroll
    for (int mt = 0; mt < 4; mt++) {
        int r0 = wm * 64 + mt * 16 + g;
        const uint32_t* U0 = (const uint32_t*)(g_UV + (size_t)s_src[r0] * 512 + h * 128);
        const uint32_t* V0 = (const uint32_t*)(g_UV + (size_t)s_dst[r0] * 512 + 256 + h * 128);
        const uint32_t* U1 = (const uint32_t*)(g_UV + (size_t)s_src[r0 + 8] * 512 + h * 128);
        const uint32_t* V1 = (const uint32_t*)(g_UV + (size_t)s_dst[r0 + 8] * 512 + 256 + h * 128);
        #pragma unroll
        for (int nt = 0; nt < 4; nt++) {
            int co = co0 + nt * 4;
            uvp[mt][nt][0] = U0[co];
            uvp[mt][nt][1] = V0[co];
            uvp[mt][nt][2] = U1[co];
            uvp[mt][nt][3] = V1[co];
        }
    }
}

// ---------------- main fused edge MLP (256 thr, 8 warps) ----------------
__global__ __launch_bounds__(NT, 1)
void edge_mlp_split(const float* __restrict__ node,
                    const int*   __restrict__ src,
                    const int*   __restrict__ dst,
                    const float* __restrict__ b2,
                    const float* __restrict__ W3,
                    const float* __restrict__ b3,
                    float* __restrict__ out, int E)
{
    extern __shared__ char smc[];
    const uint32_t smb = smem_u32(smc);
    float* smf = (float*)smc;
    int* s_src = (int*)(smc + OFF_SRC);
    int* s_dst = (int*)(smc + OFF_DST);

    const int tid = threadIdx.x, lane = tid & 31;
    const int g = lane >> 2, t = lane & 3;
    const int wid = tid >> 5, wm = wid >> 2, wn = wid & 3;
    const int e0 = blockIdx.x * TE;
    const int nedge = min(TE, E - e0);

    issue_blk(smb, tid, 0); CP_COMMIT();
    issue_blk(smb, tid, 1); CP_COMMIT();

    // gather h_i/h_j -> f16 smem (one rounding); src/dst to smem
    #pragma unroll 4
    for (int i = 0; i < 16; i++) {
        int idx = tid + i * NT;
        int m = idx >> 5, c4 = idx & 31;
        int e = min(e0 + m, E - 1);
        int si = src[e], di = dst[e];
        if (c4 == 0) { s_src[m] = si; s_dst[m] = di; }
        float4 vi = ((const float4*)node)[(size_t)si * 32 + c4];
        float4 vj = ((const float4*)node)[(size_t)di * 32 + c4];
        *(uint2*)(smc + OFF_HI + m * STRH + c4 * 8) =
            make_uint2(f2h2(vi.x, vi.y), f2h2(vi.z, vi.w));
        *(uint2*)(smc + OFF_HJ + m * STRH + c4 * 8) =
            make_uint2(f2h2(vj.x, vj.y), f2h2(vj.z, vj.w));
    }
    for (int i = tid; i < 128; i += NT) smf[OFF_B2 / 4 + i] = b2[i];
    for (int i = tid; i < 256; i += NT) smf[OFF_W3 / 4 + i] = W3[i];
    if (tid < 2) smf[OFF_B3 / 4 + tid] = b3[tid];
    __syncthreads();

    // prefetch half-0 UV fragments (latency hidden by weight-block wait below)
    uint32_t uvp[4][4][4];
    prefetch_uv(uvp, 0, s_src, s_dst, wm, wn, g, t);

    const int aRow = lane & 15;
    const int aKoff = ((lane >> 4) << 3) * 2;
    const uint32_t hiBase = smb + OFF_HI + (wm * 64 + aRow) * STRH + aKoff;
    const uint32_t hjBase = smb + OFF_HJ + (wm * 64 + aRow) * STRH + aKoff;
    const uint32_t xBase  = smb + OFF_X1 + (wm * 64 + aRow) * STRX + aKoff;
    const int nl = ((lane >> 4) << 3) + (lane & 7);
    const uint32_t bOff = (lane & 8) ? 16u : 0u;

    // ================= layer 1: two n-halves, 2 weight-block phases each =================
    for (int h = 0; h < 2; h++) {
        // acc init = U[src] + V[dst] from prefetched regs (b1 folded into U)
        float accL1[4][4][4];
        #pragma unroll
        for (int mt = 0; mt < 4; mt++)
            #pragma unroll
            for (int nt = 0; nt < 4; nt++) {
                float2 u0 = __half22float2(*(__half2*)&uvp[mt][nt][0]);
                float2 v0 = __half22float2(*(__half2*)&uvp[mt][nt][1]);
                float2 u1 = __half22float2(*(__half2*)&uvp[mt][nt][2]);
                float2 v1 = __half22float2(*(__half2*)&uvp[mt][nt][3]);
                accL1[mt][nt][0] = u0.x + v0.x; accL1[mt][nt][1] = u0.y + v0.y;
                accL1[mt][nt][2] = u1.x + v1.x; accL1[mt][nt][3] = u1.y + v1.y;
            }

        #pragma unroll
        for (int p = 0; p < 2; p++) {
            const int ph = h * 2 + p, d = ph & 1;
            // prefetch half-1 UV during h=0's second mma phase (uvp consumed above)
            if (h == 0 && p == 1)
                prefetch_uv(uvp, 1, s_src, s_dst, wm, wn, g, t);
            CP_WAIT(1);
            __syncthreads();

            #pragma unroll
            for (int s = 0; s < 8; s++) {
                uint32_t fi[4][4], fj[4][4], aF[4][4];
                #pragma unroll
                for (int mt = 0; mt < 4; mt++) {
                    ldm4(fi[mt], hiBase + mt * (16 * STRH) + s * 32);
                    ldm4(fj[mt], hjBase + mt * (16 * STRH) + s * 32);
                }
                #pragma unroll
                for (int mt = 0; mt < 4; mt++)
                    #pragma unroll
                    for (int x = 0; x < 4; x++)
                        aF[mt][x] = p ? hmul2u(fi[mt][x], fj[mt][x])
                                      : habs_sub2(fi[mt][x], fj[mt][x]);
                uint32_t bF[2][4];
                #pragma unroll
                for (int np = 0; np < 2; np++)
                    ldm4(bF[np], smb + OFF_W + d * WBLK
                                 + (wn * 32 + np * 16 + nl) * STRH + bOff + s * 32);
                #pragma unroll
                for (int mt = 0; mt < 4; mt++) {
                    mma16(accL1[mt][0], aF[mt], bF[0][0], bF[0][1]);
                    mma16(accL1[mt][1], aF[mt], bF[0][2], bF[0][3]);
                    mma16(accL1[mt][2], aF[mt], bF[1][0], bF[1][1]);
                    mma16(accL1[mt][3], aF[mt], bF[1][2], bF[1][3]);
                }
            }
            __syncthreads();
            if (ph + 2 <= 5) { issue_blk(smb, tid, ph + 2); CP_COMMIT(); }
        }

        // x1 = f16(relu(acc)) -> smem
        #pragma unroll
        for (int mt = 0; mt < 4; mt++) {
            int r = wm * 64 + mt * 16 + g;
            #pragma unroll
            for (int nt = 0; nt < 4; nt++) {
                int col = h * 128 + wn * 32 + nt * 8 + 2 * t;
                float* A = accL1[mt][nt];
                *(uint32_t*)(smc + OFF_X1 + r * STRX + col * 2) =
                    f2h2(fmaxf(A[0], 0.f), fmaxf(A[1], 0.f));
                *(uint32_t*)(smc + OFF_X1 + (r + 8) * STRX + col * 2) =
                    f2h2(fmaxf(A[2], 0.f), fmaxf(A[3], 0.f));
            }
        }
    }

    // ================= layer 2: 2 weight-block phases =================
    float accL2[4][4][4];
    #pragma unroll
    for (int mt = 0; mt < 4; mt++)
        #pragma unroll
        for (int nt = 0; nt < 4; nt++) {
            int col = wn * 32 + nt * 8 + 2 * t;
            float v0 = smf[OFF_B2 / 4 + col], v1 = smf[OFF_B2 / 4 + col + 1];
            accL2[mt][nt][0] = v0; accL2[mt][nt][1] = v1;
            accL2[mt][nt][2] = v0; accL2[mt][nt][3] = v1;
        }

    #pragma unroll
    for (int p = 0; p < 2; p++) {
        const int ph = 4 + p, d = ph & 1;
        if (ph < 5) CP_WAIT(1); else CP_WAIT(0);
        __syncthreads();   // also orders x1 stores before reads

        #pragma unroll
        for (int s = 0; s < 8; s++) {
            uint32_t aF[4][4];
            #pragma unroll
            for (int mt = 0; mt < 4; mt++)
                ldm4(aF[mt], xBase + mt * (16 * STRX) + (p * 128 + s * 16) * 2);
            uint32_t bF[2][4];
            #pragma unroll
            for (int np = 0; np < 2; np++)
                ldm4(bF[np], smb + OFF_W + d * WBLK
                             + (wn * 32 + np * 16 + nl) * STRH + bOff + s * 32);
            #pragma unroll
            for (int mt = 0; mt < 4; mt++) {
                mma16(accL2[mt][0], aF[mt], bF[0][0], bF[0][1]);
                mma16(accL2[mt][1], aF[mt], bF[0][2], bF[0][3]);
                mma16(accL2[mt][2], aF[mt], bF[1][0], bF[1][1]);
                mma16(accL2[mt][3], aF[mt], bF[1][2], bF[1][3]);
            }
        }
        __syncthreads();
    }

    // ================= layer 3: register relu.W3 + quad shuffle-reduce =================
    float* s_red = (float*)(smc + OFF_W);   // weight region dead: [128][8] f32
    #pragma unroll
    for (int mt = 0; mt < 4; mt++) {
        int r = wm * 64 + mt * 16 + g;
        float p00 = 0.f, p01 = 0.f, p10 = 0.f, p11 = 0.f;
        #pragma unroll
        for (int nt = 0; nt < 4; nt++) {
            float* A = accL2[mt][nt];
            int col = wn * 32 + nt * 8 + 2 * t;
            float w00 = smf[OFF_W3 / 4 + 2 * col],     w01 = smf[OFF_W3 / 4 + 2 * col + 1];
            float w10 = smf[OFF_W3 / 4 + 2 * col + 2], w11 = smf[OFF_W3 / 4 + 2 * col + 3];
            float x0 = fmaxf(A[0], 0.f), x1v = fmaxf(A[1], 0.f);
            float x2v = fmaxf(A[2], 0.f), x3v = fmaxf(A[3], 0.f);
            p00 += x0 * w00 + x1v * w10;
            p01 += x0 * w01 + x1v * w11;
            p10 += x2v * w00 + x3v * w10;
            p11 += x2v * w01 + x3v * w11;
        }
        p00 += __shfl_xor_sync(0xFFFFFFFFu, p00, 1);
        p00 += __shfl_xor_sync(0xFFFFFFFFu, p00, 2);
        p01 += __shfl_xor_sync(0xFFFFFFFFu, p01, 1);
        p01 += __shfl_xor_sync(0xFFFFFFFFu, p01, 2);
        p10 += __shfl_xor_sync(0xFFFFFFFFu, p10, 1);
        p10 += __shfl_xor_sync(0xFFFFFFFFu, p10, 2);
        p11 += __shfl_xor_sync(0xFFFFFFFFu, p11, 1);
        p11 += __shfl_xor_sync(0xFFFFFFFFu, p11, 2);
        if (t == 0) {
            s_red[r * 8 + wn * 2 + 0] = p00;
            s_red[r * 8 + wn * 2 + 1] = p01;
            s_red[(r + 8) * 8 + wn * 2 + 0] = p10;
            s_red[(r + 8) * 8 + wn * 2 + 1] = p11;
        }
    }
    __syncthreads();

    {
        int row = tid >> 1, cc = tid & 1;
        float sum = smf[OFF_B3 / 4 + cc]
                  + s_red[row * 8 + 0 + cc] + s_red[row * 8 + 2 + cc]
                  + s_red[row * 8 + 4 + cc] + s_red[row * 8 + 6 + cc];
        if (row < nedge) out[(size_t)(e0 + row) * 2 + cc] = sum;
    }
}

extern "C" void kernel_launch(void* const* d_in, const int* in_sizes, int n_in,
                              void* d_out, int out_size)
{
    const float* node = (const float*)d_in[0];
    const int*   src  = (const int*)  d_in[1];
    const int*   dst  = (const int*)  d_in[2];
    const float* W1   = (const float*)d_in[3];
    const float* b1   = (const float*)d_in[4];
    const float* W2   = (const float*)d_in[5];
    const float* b2   = (const float*)d_in[6];
    const float* W3   = (const float*)d_in[7];
    const float* b3   = (const float*)d_in[8];
    float* out = (float*)d_out;

    const int E = in_sizes[1];
    const int nnode = in_sizes[0] / 128;

    {   // prep 1: weight rounding/transpose
        int total = 512 * 128 + 256 * 256 + 128 * 256;
        prep_w<<<(total + 255) / 256, 256>>>(W1, W2);
    }
    {   // prep 2: UV = node @ [W1a|W1b] + [b1|0]
        cudaFuncSetAttribute(uv_kernel,
                             cudaFuncAttributeMaxDynamicSharedMemorySize, UV_SMEM);
        dim3 grid((nnode + 127) / 128, 4);
        uv_kernel<<<grid, 256, UV_SMEM>>>(node, b1, nnode);
    }

    cudaFuncSetAttribute(edge_mlp_split,
                         cudaFuncAttributeMaxDynamicSharedMemorySize, SMEM_BYTES);
    const int grid = (E + TE - 1) / TE;
    edge_mlp_split<<<grid, NT, SMEM_BYTES>>>(node, src, dst, b2, W3, b3, out, E);
}